// round 14
// baseline (speedup 1.0000x reference)
#include <cuda_runtime.h>
#include <cstdint>

// Problem constants
#define HWX   65536          // 256*256
#define NPIX  131072ul       // 2*256*256
#define CCH   320
#define SPL   160

// Scratch (static __device__ — no allocations allowed)
__device__ float g_mean[131072];
__device__ float g_rstd[131072];
__device__ float g_wcT[320 * 1024];         // combined weights, TRANSPOSED [k][m], cols 960..1023 zero
__device__ float g_bc[1024];                // combined biases (padded, rows>=960 zero)
__device__ float g_qkv[960ul * 131072ul];   // GEMM output: rows 0..479 = h(q,k,v), 480..959 = v(q,k,v)
__device__ float g_qkvT[480ul * 131072ul];  // vertical qkv, H-major
__device__ float g_avs[160ul * 131072ul];   // vertical attn out, [c][b][w][h]

// ---------------------------------------------------------------------------
// packed fp32x2 FMA (sm_103 FFMA2) — 2x fp32 fma throughput
// ---------------------------------------------------------------------------
__device__ __forceinline__ float2 ffma2(float2 a, float2 b, float2 c) {
    float2 d;
    asm("{ .reg .b64 ra, rb, rc, rd;\n\t"
        "mov.b64 ra, {%2, %3}; mov.b64 rb, {%4, %5}; mov.b64 rc, {%6, %7};\n\t"
        "fma.rn.f32x2 rd, ra, rb, rc;\n\t"
        "mov.b64 {%0, %1}, rd; }"
        : "=f"(d.x), "=f"(d.y)
        : "f"(a.x), "f"(a.y), "f"(b.x), "f"(b.y), "f"(c.x), "f"(c.y));
    return d;
}

// ---------------------------------------------------------------------------
// 1) Per-pixel LayerNorm stats over channels
// ---------------------------------------------------------------------------
__global__ void ln_stats_kernel(const float* __restrict__ x) {
    int p  = blockIdx.x * 256 + threadIdx.x;
    int b  = p >> 16;
    int hw = p & 65535;
    const float* xp = x + (size_t)b * CCH * HWX + hw;
    float s = 0.f, s2 = 0.f;
#pragma unroll 4
    for (int c = 0; c < CCH; c++) {
        float v = __ldg(xp + (size_t)c * HWX);
        s += v; s2 += v * v;
    }
    float mu  = s * (1.f / 320.f);
    float var = s2 * (1.f / 320.f) - mu * mu;
    g_mean[p] = mu;
    g_rstd[p] = rsqrtf(var + 1e-5f);
}

// ---------------------------------------------------------------------------
// 2) Fold conv into QKV; store TRANSPOSED fp32 [k][m]. Cols 960..1023 zero.
// ---------------------------------------------------------------------------
__global__ void combine_w_kernel(
    const float* __restrict__ conv_w, const float* __restrict__ conv_b,
    const float* w0, const float* b0, const float* w1, const float* b1,
    const float* w2, const float* b2, const float* w3, const float* b3,
    const float* w4, const float* b4, const float* w5, const float* b5)
{
    int r = blockIdx.x;            // 0..1023  (output row of Wc)
    int c = threadIdx.x;           // 0..319   (input channel = k)
    if (r >= 960) {
        g_wcT[c * 1024 + r] = 0.f;
        if (c == 0) g_bc[r] = 0.f;
        return;
    }
    int g = r / 160, ro = r % 160;
    const float* wg; const float* bg;
    switch (g) {
        case 0: wg = w0; bg = b0; break;
        case 1: wg = w1; bg = b1; break;
        case 2: wg = w2; bg = b2; break;
        case 3: wg = w3; bg = b3; break;
        case 4: wg = w4; bg = b4; break;
        default: wg = w5; bg = b5; break;
    }
    int half = (g >= 3) ? 1 : 0;
    __shared__ float wrow[160];
    if (threadIdx.x < 160) wrow[threadIdx.x] = __ldg(wg + ro * 160 + threadIdx.x);
    __syncthreads();
    const float* cw = conv_w + (size_t)half * 160 * 320 + c;
    float s = 0.f;
#pragma unroll 4
    for (int d = 0; d < 160; d++)
        s += wrow[d] * __ldg(cw + d * 320);
    g_wcT[c * 1024 + r] = s;
    if (c == 0) {
        float sb = __ldg(bg + ro);
        const float* cb = conv_b + half * 160;
        for (int d = 0; d < 160; d++) sb += wrow[d] * __ldg(cb + d);
        g_bc[r] = sb;
    }
}

// ---------------------------------------------------------------------------
// 3) FFMA2 GEMM: qkv[960][131072] = Wc @ LN(x) + bc   (LN fused in B staging)
//    R14: BM=64 x BN=256 (grid 15x512 — 960 = 15*64, ZERO padding waste).
//    BK=16, 256 threads, double-buffered smem, warps as 2m x 4n,
//    warp tile 32x64, thread tile 8x8 — inner loop identical to R13.
// ---------------------------------------------------------------------------
__global__ void __launch_bounds__(256, 2) gemm_qkv_kernel(
    const float* __restrict__ x,
    const float* __restrict__ lnw, const float* __restrict__ lnb)
{
    __shared__ float As[2][16][64];     // [stage][k][m]
    __shared__ float Bs[2][16][256];    // [stage][k][n]
    __shared__ float sLnw[320], sLnb[320];

    int tid  = threadIdx.x;
    int wid  = tid >> 5, lane = tid & 31;
    int ly   = lane >> 3;              // 0..3  -> m sub-tile of 8
    int lx   = lane & 7;               // 0..7  -> n sub-tile (2x float4)
    int wm   = (wid & 1) * 32;         // warp m offset (2 groups x 32 = 64)
    int wn   = (wid >> 1) * 64;        // warp n offset (4 groups x 64 = 256)
    int m0   = blockIdx.x * 64;        // 0..896, all rows real (no padding)
    int n0   = blockIdx.y * 256;

    // A staging: thread -> (k row ak, m quad am)
    int ak = tid >> 4;                 // 0..15
    int am = tid & 15;                 // 0..15 (16 quads = 64 floats)
    // B staging: thread -> (n quad qn fixed, k rows qk+4i)
    int qn = tid & 63;                 // 0..63 (64 quads = 256 floats)
    int qk = tid >> 6;                 // 0..3

    // ln params to smem — STRIDED (320 entries, 256 threads)
    for (int i = tid; i < 320; i += 256) {
        sLnw[i] = __ldg(lnw + i);
        sLnb[i] = __ldg(lnb + i);
    }

    int b = n0 >> 16;
    const float* xb = x + (size_t)b * CCH * HWX + (n0 & 65535);
    float4 mean4 = *(const float4*)&g_mean[n0 + qn * 4];
    float4 rstd4 = *(const float4*)&g_rstd[n0 + qn * 4];
    __syncthreads();                   // sLnw/sLnb ready

    float4 Arq, Brq[4];
#define LOAD_CHUNK(k0)                                                        \
    do {                                                                      \
        Arq = *(const float4*)&g_wcT[(size_t)((k0) + ak) * 1024 + m0 + am * 4]; \
        _Pragma("unroll")                                                     \
        for (int i = 0; i < 4; i++) {                                         \
            int k = (k0) + qk + i * 4;                                        \
            Brq[i] = *(const float4*)&xb[(size_t)k * HWX + qn * 4];           \
        }                                                                     \
    } while (0)
#define STORE_CHUNK(st, k0)                                                   \
    do {                                                                      \
        *(float4*)&As[st][ak][am * 4] = Arq;                                  \
        _Pragma("unroll")                                                     \
        for (int i = 0; i < 4; i++) {                                         \
            int kk = qk + i * 4;                                              \
            float lw = sLnw[(k0) + kk], lbv = sLnb[(k0) + kk];                \
            float4 v = Brq[i], o;                                             \
            o.x = fmaf((v.x - mean4.x) * rstd4.x, lw, lbv);                   \
            o.y = fmaf((v.y - mean4.y) * rstd4.y, lw, lbv);                   \
            o.z = fmaf((v.z - mean4.z) * rstd4.z, lw, lbv);                   \
            o.w = fmaf((v.w - mean4.w) * rstd4.w, lw, lbv);                   \
            *(float4*)&Bs[st][kk][qn * 4] = o;                                \
        }                                                                     \
    } while (0)

    float2 acc[8][4];
#pragma unroll
    for (int i = 0; i < 8; i++)
#pragma unroll
        for (int j = 0; j < 4; j++) acc[i][j] = make_float2(0.f, 0.f);

    LOAD_CHUNK(0);
    STORE_CHUNK(0, 0);
    __syncthreads();

    for (int c = 0; c < 20; c++) {
        int cur = c & 1;
        if (c < 19) LOAD_CHUNK((c + 1) * 16);
#pragma unroll
        for (int kk = 0; kk < 16; kk++) {
            float4 a0 = *(const float4*)&As[cur][kk][wm + ly * 8];
            float4 a1 = *(const float4*)&As[cur][kk][wm + ly * 8 + 4];
            float4 b0 = *(const float4*)&Bs[cur][kk][wn + lx * 4];
            float4 b1 = *(const float4*)&Bs[cur][kk][wn + 32 + lx * 4];
            float2 bv0 = make_float2(b0.x, b0.y);
            float2 bv1 = make_float2(b0.z, b0.w);
            float2 bv2 = make_float2(b1.x, b1.y);
            float2 bv3 = make_float2(b1.z, b1.w);
            float a[8] = {a0.x, a0.y, a0.z, a0.w, a1.x, a1.y, a1.z, a1.w};
#pragma unroll
            for (int i = 0; i < 8; i++) {
                float2 av = make_float2(a[i], a[i]);
                acc[i][0] = ffma2(av, bv0, acc[i][0]);
                acc[i][1] = ffma2(av, bv1, acc[i][1]);
                acc[i][2] = ffma2(av, bv2, acc[i][2]);
                acc[i][3] = ffma2(av, bv3, acc[i][3]);
            }
        }
        if (c < 19) {
            STORE_CHUNK(1 - cur, (c + 1) * 16);
            __syncthreads();
        }
    }

    // epilogue: all rows < 960 by construction (no guard needed)
#pragma unroll
    for (int i = 0; i < 8; i++) {
        int r = m0 + wm + ly * 8 + i;
        float bias = g_bc[r];
        float* op = g_qkv + (size_t)r * NPIX + n0 + wn;
        float4 o0 = make_float4(acc[i][0].x + bias, acc[i][0].y + bias,
                                acc[i][1].x + bias, acc[i][1].y + bias);
        float4 o1 = make_float4(acc[i][2].x + bias, acc[i][2].y + bias,
                                acc[i][3].x + bias, acc[i][3].y + bias);
        *(float4*)(op + lx * 4)      = o0;
        *(float4*)(op + 32 + lx * 4) = o1;
    }
#undef LOAD_CHUNK
#undef STORE_CHUNK
}

// ---------------------------------------------------------------------------
// 4) Transpose vertical qkv rows (960 matrices of 256x256) into H-major order
// ---------------------------------------------------------------------------
__global__ void transpose_qkv_kernel() {
    __shared__ float tile[32][33];
    int m = blockIdx.z;
    const float* s = g_qkv + 480ul * NPIX + (size_t)m * HWX;
    float* d       = g_qkvT + (size_t)m * HWX;
    int x0 = blockIdx.x * 32, y0 = blockIdx.y * 32;
    int tx = threadIdx.x, ty = threadIdx.y;
#pragma unroll
    for (int i = 0; i < 4; i++)
        tile[ty + i * 8][tx] = s[(size_t)(y0 + ty + i * 8) * 256 + x0 + tx];
    __syncthreads();
#pragma unroll
    for (int i = 0; i < 4; i++)
        d[(size_t)(x0 + ty + i * 8) * 256 + y0 + tx] = tile[tx][ty + i * 8];
}

// ---------------------------------------------------------------------------
// 5) Axial attention v2: 128 threads/block, 2 queries per thread (t, t+128).
// ---------------------------------------------------------------------------
template <int VMODE>
__global__ void __launch_bounds__(128) attn_kernel(float* __restrict__ out)
{
    __shared__ float Ks[128 * 36];
    __shared__ float Vs[128 * 36];
    int hd  = blockIdx.x;        // 0..4
    int seq = blockIdx.y;        // 0..511
    int t   = threadIdx.x;       // 0..127; queries t and t+128

    const float* qkv = (VMODE == 0) ? g_qkv : g_qkvT;

    const float* qa = qkv + (size_t)(hd * 32) * NPIX + (size_t)seq * 256 + t;
    const float* kb = qkv + (size_t)(160 + hd * 32) * NPIX + (size_t)seq * 256;
    const float* vb = qkv + (size_t)(320 + hd * 32) * NPIX + (size_t)seq * 256;

    float2 q2a[16], q2b[16];
#pragma unroll
    for (int c = 0; c < 16; c++) {
        q2a[c].x = __ldg(qa + (size_t)(2 * c) * NPIX);
        q2a[c].y = __ldg(qa + (size_t)(2 * c + 1) * NPIX);
        q2b[c].x = __ldg(qa + (size_t)(2 * c) * NPIX + 128);
        q2b[c].y = __ldg(qa + (size_t)(2 * c + 1) * NPIX + 128);
    }

    float mxa = -1e30f, la = 0.f;
    float mxb = -1e30f, lb = 0.f;
    float2 acca[16], accb[16];
#pragma unroll
    for (int c = 0; c < 16; c++) { acca[c] = make_float2(0.f, 0.f); accb[c] = make_float2(0.f, 0.f); }
    const float scale = 0.17677669529663688f;   // 1/sqrt(32)

    for (int chunk = 0; chunk < 2; chunk++) {
        int j0 = chunk * 128;
        __syncthreads();
#pragma unroll
        for (int i = 0; i < 32; i++) {
            Ks[t * 36 + i] = __ldg(kb + (size_t)i * NPIX + j0 + t);
            Vs[t * 36 + i] = __ldg(vb + (size_t)i * NPIX + j0 + t);
        }
        __syncthreads();
        for (int j = 0; j < 128; j++) {
            const float4* k4 = (const float4*)(Ks + j * 36);
            const float4* v4 = (const float4*)(Vs + j * 36);
            float2 da = make_float2(0.f, 0.f);
            float2 db = make_float2(0.f, 0.f);
#pragma unroll
            for (int c = 0; c < 8; c++) {
                float4 kv = k4[c];
                float2 k01 = make_float2(kv.x, kv.y);
                float2 k23 = make_float2(kv.z, kv.w);
                da = ffma2(q2a[2 * c],     k01, da);
                da = ffma2(q2a[2 * c + 1], k23, da);
                db = ffma2(q2b[2 * c],     k01, db);
                db = ffma2(q2b[2 * c + 1], k23, db);
            }
            float sa = (da.x + da.y) * scale;
            float sb = (db.x + db.y) * scale;
            if (sa > mxa) {
                float corr = __expf(mxa - sa);
                mxa = sa; la *= corr;
#pragma unroll
                for (int c = 0; c < 16; c++) { acca[c].x *= corr; acca[c].y *= corr; }
            }
            if (sb > mxb) {
                float corr = __expf(mxb - sb);
                mxb = sb; lb *= corr;
#pragma unroll
                for (int c = 0; c < 16; c++) { accb[c].x *= corr; accb[c].y *= corr; }
            }
            float pa = __expf(sa - mxa);
            float pb = __expf(sb - mxb);
            la += pa; lb += pb;
            float2 ppa = make_float2(pa, pa);
            float2 ppb = make_float2(pb, pb);
#pragma unroll
            for (int c = 0; c < 8; c++) {
                float4 vv = v4[c];
                float2 v01 = make_float2(vv.x, vv.y);
                float2 v23 = make_float2(vv.z, vv.w);
                acca[2 * c]     = ffma2(ppa, v01, acca[2 * c]);
                acca[2 * c + 1] = ffma2(ppa, v23, acca[2 * c + 1]);
                accb[2 * c]     = ffma2(ppb, v01, accb[2 * c]);
                accb[2 * c + 1] = ffma2(ppb, v23, accb[2 * c + 1]);
            }
        }
    }
    float rla = 1.f / la;
    float rlb = 1.f / lb;
    if (VMODE == 0) {
        int b = seq >> 8, h = seq & 255;
        float* o = out + (size_t)(b * 160 + hd * 32) * HWX + h * 256 + t;
#pragma unroll
        for (int c = 0; c < 16; c++) {
            o[(size_t)(2 * c) * HWX]           = acca[c].x * rla;
            o[(size_t)(2 * c + 1) * HWX]       = acca[c].y * rla;
            o[(size_t)(2 * c) * HWX + 128]     = accb[c].x * rlb;
            o[(size_t)(2 * c + 1) * HWX + 128] = accb[c].y * rlb;
        }
    } else {
        float* o = g_avs + (size_t)(hd * 32) * NPIX + (size_t)seq * 256 + t;
#pragma unroll
        for (int c = 0; c < 16; c++) {
            o[(size_t)(2 * c) * NPIX]           = acca[c].x * rla;
            o[(size_t)(2 * c + 1) * NPIX]       = acca[c].y * rla;
            o[(size_t)(2 * c) * NPIX + 128]     = accb[c].x * rlb;
            o[(size_t)(2 * c + 1) * NPIX + 128] = accb[c].y * rlb;
        }
    }
}

// ---------------------------------------------------------------------------
// 6) Final transpose of vertical attention output into d_out batches 2..3
// ---------------------------------------------------------------------------
__global__ void transpose_av_kernel(float* __restrict__ outp) {
    __shared__ float tile[32][33];
    int z = blockIdx.z;
    int b = z / 160, c = z % 160;
    const float* s = g_avs + (size_t)(c * 2 + b) * HWX;
    float* d = outp + 2ul * 160ul * HWX + (size_t)z * HWX;
    int x0 = blockIdx.x * 32, y0 = blockIdx.y * 32;
    int tx = threadIdx.x, ty = threadIdx.y;
#pragma unroll
    for (int i = 0; i < 4; i++)
        tile[ty + i * 8][tx] = s[(size_t)(y0 + ty + i * 8) * 256 + x0 + tx];
    __syncthreads();
#pragma unroll
    for (int i = 0; i < 4; i++)
        d[(size_t)(x0 + ty + i * 8) * 256 + y0 + tx] = tile[tx][ty + i * 8];
}

// ---------------------------------------------------------------------------
extern "C" void kernel_launch(void* const* d_in, const int* in_sizes, int n_in,
                              void* d_out, int out_size)
{
    const float* x      = (const float*)d_in[0];
    const float* lnw    = (const float*)d_in[1];
    const float* lnb    = (const float*)d_in[2];
    const float* conv_w = (const float*)d_in[3];
    const float* conv_b = (const float*)d_in[4];
    float* out = (float*)d_out;

    ln_stats_kernel<<<512, 256>>>(x);
    combine_w_kernel<<<1024, 320>>>(conv_w, conv_b,
        (const float*)d_in[5],  (const float*)d_in[6],
        (const float*)d_in[7],  (const float*)d_in[8],
        (const float*)d_in[9],  (const float*)d_in[10],
        (const float*)d_in[11], (const float*)d_in[12],
        (const float*)d_in[13], (const float*)d_in[14],
        (const float*)d_in[15], (const float*)d_in[16]);
    gemm_qkv_kernel<<<dim3(15, 512), 256>>>(x, lnw, lnb);
    transpose_qkv_kernel<<<dim3(8, 8, 960), dim3(32, 8)>>>();

    attn_kernel<0><<<dim3(5, 512), 128>>>(out);
    attn_kernel<1><<<dim3(5, 512), 128>>>(out);
    transpose_av_kernel<<<dim3(8, 8, 320), dim3(32, 8)>>>(out);
}